// round 8
// baseline (speedup 1.0000x reference)
#include <cuda_runtime.h>
#include <cuda_bf16.h>
#include <mma.h>
#include <math.h>
#include <stdint.h>

using namespace nvcuda;

#define D 128
#define NHEADS 8
#define NMAX 50000

// blocks [0, FSPLIT) use FFMA body; [FSPLIT, nblk) use wmma bf16x3 body
#define FSPLIT 160

// ---- scratch (no allocations allowed; device globals) ----
__device__ float g_Q[NMAX * D];
__device__ float g_K[NMAX * D];
__device__ float g_V[NMAX * D];
__device__ float g_wV[NMAX * D];
__device__ float g_z[NMAX * NHEADS];
__device__ float g_h[NMAX * D];
__device__ float g_g[NMAX * D];
// precomputed bf16 hi/lo splits
__device__ __nv_bfloat16 g_xh[NMAX * D];
__device__ __nv_bfloat16 g_xl[NMAX * D];
__device__ __nv_bfloat16 g_gh[NMAX * D];
__device__ __nv_bfloat16 g_gl[NMAX * D];
__device__ __nv_bfloat16 g_Wh[4 * D * D];
__device__ __nv_bfloat16 g_Wl[4 * D * D];

// ============================================================
// shared-memory union layout (static, < 48KB)
// ============================================================
#define SM_BYTES 48128
#define W_AH 0
#define W_AL 10240
#define W_BH 20480
#define W_BL 29184
#define W_ST 37888
#define AS_LD 40     // bf16 elems (80 B row stride)
#define BS_LD 136    // bf16 elems (272 B row stride)
#define ST_LD 20     // f32 elems (80 B)

// ============================================================
// FFMA body (round-1 proven): 128x128 tile, 8x8 microtile
// ============================================================
template <int MODE>
__device__ __forceinline__ void gemm_ffma(
    char* smbuf,
    const float* __restrict__ A, const float* __restrict__ W,
    const float* __restrict__ bias, float* __restrict__ C,
    const float* __restrict__ R, int M)
{
    float (*As)[129] = reinterpret_cast<float(*)[129]>(smbuf);
    float (*Bs)[128] = reinterpret_cast<float(*)[128]>(smbuf + 16512);

    const int tid  = threadIdx.x;
    const int tx   = tid & 15;
    const int ty   = tid >> 4;
    const int row0 = blockIdx.x * 128;

    float acc[8][8];
#pragma unroll
    for (int i = 0; i < 8; i++)
#pragma unroll
        for (int j = 0; j < 8; j++) acc[i][j] = 0.0f;

    const int arow = tid >> 3;
    const int acol = (tid & 7) << 2;
    const int brow = tid >> 5;
    const int bcol = (tid & 31) << 2;

    for (int kk = 0; kk < 128; kk += 32) {
        __syncthreads();
#pragma unroll
        for (int p = 0; p < 4; p++) {
            int r = row0 + arow + p * 32;
            float4 v = make_float4(0.f, 0.f, 0.f, 0.f);
            if (r < M) v = *(const float4*)(A + (size_t)r * 128 + kk + acol);
            int m = arow + p * 32;
            As[acol + 0][m] = v.x;
            As[acol + 1][m] = v.y;
            As[acol + 2][m] = v.z;
            As[acol + 3][m] = v.w;
        }
#pragma unroll
        for (int p = 0; p < 4; p++) {
            int r = kk + brow + p * 8;
            *(float4*)&Bs[brow + p * 8][bcol] =
                *(const float4*)(W + (size_t)r * 128 + bcol);
        }
        __syncthreads();

#pragma unroll
        for (int k = 0; k < 32; k++) {
            float a[8];
#pragma unroll
            for (int i = 0; i < 8; i++) a[i] = As[k][ty * 8 + i];
            float4 b0 = *(float4*)&Bs[k][tx * 8];
            float4 b1 = *(float4*)&Bs[k][tx * 8 + 4];
            float b[8] = {b0.x, b0.y, b0.z, b0.w, b1.x, b1.y, b1.z, b1.w};
#pragma unroll
            for (int i = 0; i < 8; i++)
#pragma unroll
                for (int j = 0; j < 8; j++)
                    acc[i][j] = fmaf(a[i], b[j], acc[i][j]);
        }
    }

    const int c0 = tx * 8;
    float4 bb0 = *(const float4*)(bias + c0);
    float4 bb1 = *(const float4*)(bias + c0 + 4);
    float bb[8] = {bb0.x, bb0.y, bb0.z, bb0.w, bb1.x, bb1.y, bb1.z, bb1.w};
#pragma unroll
    for (int i = 0; i < 8; i++) {
        int r = row0 + ty * 8 + i;
        if (r >= M) continue;
        float v[8];
#pragma unroll
        for (int j = 0; j < 8; j++) {
            float val = acc[i][j] + bb[j];
            if (MODE == 1)
                val = R[(size_t)r * 128 + c0 + j] + fmaxf(val, 0.0f);
            v[j] = val;
        }
        *(float4*)(C + (size_t)r * 128 + c0)     = make_float4(v[0], v[1], v[2], v[3]);
        *(float4*)(C + (size_t)r * 128 + c0 + 4) = make_float4(v[4], v[5], v[6], v[7]);
    }
}

// ============================================================
// WMMA bf16x3 body with PRE-SPLIT bf16 inputs (no cvt in loop).
// 128x128 tile, 8 warps 2(m)x4(n), warp = 64x32, BK=32.
// ============================================================
template <int MODE>
__device__ __forceinline__ void gemm_wmma(
    char* smbuf,
    const __nv_bfloat16* __restrict__ Agh, const __nv_bfloat16* __restrict__ Agl,
    const __nv_bfloat16* __restrict__ Wgh, const __nv_bfloat16* __restrict__ Wgl,
    const float* __restrict__ bias, float* __restrict__ C,
    const float* __restrict__ R, int M)
{
    __nv_bfloat16* Ah = (__nv_bfloat16*)(smbuf + W_AH);
    __nv_bfloat16* Al = (__nv_bfloat16*)(smbuf + W_AL);
    __nv_bfloat16* Bh = (__nv_bfloat16*)(smbuf + W_BH);
    __nv_bfloat16* Bl = (__nv_bfloat16*)(smbuf + W_BL);

    const int tid    = threadIdx.x;
    const int warp   = tid >> 5;
    const int lane   = tid & 31;
    const int warp_m = warp & 1;
    const int warp_n = warp >> 1;
    const int row0   = blockIdx.x * 128;
    float* stg = (float*)(smbuf + W_ST) + warp * 16 * ST_LD;

    wmma::fragment<wmma::accumulator, 16, 16, 16, float> c[4][2];
#pragma unroll
    for (int im = 0; im < 4; im++)
#pragma unroll
        for (int jn = 0; jn < 2; jn++) wmma::fill_fragment(c[im][jn], 0.0f);

    const int arow = tid >> 1;          // 0..127
    const int acol = (tid & 1) * 16;    // 0 or 16
    const int brow = tid >> 3;          // 0..31
    const int bcol = (tid & 7) * 16;    // 0..112

    const uint4 zero4 = make_uint4(0u, 0u, 0u, 0u);

    for (int kk = 0; kk < 128; kk += 32) {
        __syncthreads();
        // A chunk [128 x 32] bf16 hi/lo: pure 16B copies
        {
            int r = row0 + arow;
            const uint4* sh = (const uint4*)(Agh + (size_t)r * 128 + kk + acol);
            const uint4* sl = (const uint4*)(Agl + (size_t)r * 128 + kk + acol);
            uint4* dh = (uint4*)(Ah + arow * AS_LD + acol);
            uint4* dl = (uint4*)(Al + arow * AS_LD + acol);
            if (r < M) {
                dh[0] = sh[0]; dh[1] = sh[1];
                dl[0] = sl[0]; dl[1] = sl[1];
            } else {
                dh[0] = zero4; dh[1] = zero4;
                dl[0] = zero4; dl[1] = zero4;
            }
        }
        // W chunk [32 x 128] bf16 hi/lo
        {
            const uint4* sh = (const uint4*)(Wgh + (size_t)(kk + brow) * 128 + bcol);
            const uint4* sl = (const uint4*)(Wgl + (size_t)(kk + brow) * 128 + bcol);
            uint4* dh = (uint4*)(Bh + brow * BS_LD + bcol);
            uint4* dl = (uint4*)(Bl + brow * BS_LD + bcol);
            dh[0] = sh[0]; dh[1] = sh[1];
            dl[0] = sl[0]; dl[1] = sl[1];
        }
        __syncthreads();

#pragma unroll
        for (int ks = 0; ks < 2; ks++) {
            const int k0 = ks * 16;
            wmma::fragment<wmma::matrix_b, 16, 16, 16, __nv_bfloat16, wmma::row_major> b_hi[2], b_lo[2];
#pragma unroll
            for (int jn = 0; jn < 2; jn++) {
                const int n0 = warp_n * 32 + jn * 16;
                wmma::load_matrix_sync(b_hi[jn], Bh + k0 * BS_LD + n0, BS_LD);
                wmma::load_matrix_sync(b_lo[jn], Bl + k0 * BS_LD + n0, BS_LD);
            }
#pragma unroll
            for (int im = 0; im < 4; im++) {
                const int m0 = warp_m * 64 + im * 16;
                wmma::fragment<wmma::matrix_a, 16, 16, 16, __nv_bfloat16, wmma::row_major> a_hi, a_lo;
                wmma::load_matrix_sync(a_hi, Ah + m0 * AS_LD + k0, AS_LD);
                wmma::load_matrix_sync(a_lo, Al + m0 * AS_LD + k0, AS_LD);
#pragma unroll
                for (int jn = 0; jn < 2; jn++) {
                    wmma::mma_sync(c[im][jn], a_hi, b_hi[jn], c[im][jn]);
                    wmma::mma_sync(c[im][jn], a_hi, b_lo[jn], c[im][jn]);
                    wmma::mma_sync(c[im][jn], a_lo, b_hi[jn], c[im][jn]);
                }
            }
        }
    }

    // epilogue via per-warp staging
    const int r  = lane >> 1;
    const int cc = (lane & 1) * 8;
#pragma unroll
    for (int im = 0; im < 4; im++) {
#pragma unroll
        for (int jn = 0; jn < 2; jn++) {
            wmma::store_matrix_sync(stg, c[im][jn], ST_LD, wmma::mem_row_major);
            __syncwarp();
            const int grow = row0 + warp_m * 64 + im * 16 + r;
            const int gcol = warp_n * 32 + jn * 16 + cc;
            if (grow < M) {
                float v[8];
#pragma unroll
                for (int u = 0; u < 8; u++) {
                    float val = stg[r * ST_LD + cc + u] + bias[gcol + u];
                    if (MODE == 1)
                        val = R[(size_t)grow * 128 + gcol + u] + fmaxf(val, 0.0f);
                    v[u] = val;
                }
                *(float4*)(C + (size_t)grow * 128 + gcol)     = make_float4(v[0], v[1], v[2], v[3]);
                *(float4*)(C + (size_t)grow * 128 + gcol + 4) = make_float4(v[4], v[5], v[6], v[7]);
            }
            __syncwarp();
        }
    }
}

// ============================================================
// prep: split weights (once per launch)
// ============================================================
__global__ __launch_bounds__(256) void prep_w_kernel(
    const float* __restrict__ Wq, const float* __restrict__ Wk,
    const float* __restrict__ Wv, const float* __restrict__ Wo)
{
    const float* W;
    switch (blockIdx.x) {
        case 0: W = Wq; break;
        case 1: W = Wk; break;
        case 2: W = Wv; break;
        default: W = Wo; break;
    }
    __nv_bfloat16* oh = g_Wh + (size_t)blockIdx.x * D * D;
    __nv_bfloat16* ol = g_Wl + (size_t)blockIdx.x * D * D;
    for (int i = threadIdx.x; i < D * D; i += 256) {
        float v = W[i];
        __nv_bfloat16 h = __float2bfloat16(v);
        oh[i] = h;
        ol[i] = __float2bfloat16(v - __bfloat162float(h));
    }
}

// split x -> g_xh/g_xl
__global__ __launch_bounds__(256) void split_x_kernel(
    const float* __restrict__ x, int n)
{
    int i = blockIdx.x * blockDim.x + threadIdx.x;
    int stride = gridDim.x * blockDim.x;
    for (int j = i; j < n; j += stride) {
        float v = x[j];
        __nv_bfloat16 h = __float2bfloat16(v);
        g_xh[j] = h;
        g_xl[j] = __float2bfloat16(v - __bfloat162float(h));
    }
}

// ============================================================
// hybrid GEMM kernels
// ============================================================
__global__ __launch_bounds__(256) void qkv_kernel(
    const float* __restrict__ x,
    const float* __restrict__ Wq, const float* __restrict__ bq,
    const float* __restrict__ Wk, const float* __restrict__ bk,
    const float* __restrict__ Wv, const float* __restrict__ bv, int M)
{
    __shared__ alignas(16) char smbuf[SM_BYTES];
    const float* W; const float* b; float* C; int wi;
    if (blockIdx.y == 0)      { W = Wq; b = bq; C = g_Q; wi = 0; }
    else if (blockIdx.y == 1) { W = Wk; b = bk; C = g_K; wi = 1; }
    else                      { W = Wv; b = bv; C = g_V; wi = 2; }
    if (blockIdx.x < FSPLIT)
        gemm_ffma<0>(smbuf, x, W, b, C, nullptr, M);
    else
        gemm_wmma<0>(smbuf, g_xh, g_xl,
                     g_Wh + (size_t)wi * D * D, g_Wl + (size_t)wi * D * D,
                     b, C, nullptr, M);
}

__global__ __launch_bounds__(256) void out_gemm_kernel(
    const float* __restrict__ Wo, const float* __restrict__ bo,
    float* __restrict__ out, int M)
{
    __shared__ alignas(16) char smbuf[SM_BYTES];
    if (blockIdx.x < FSPLIT)
        gemm_ffma<1>(smbuf, g_g, Wo, bo, out, g_h, M);
    else
        gemm_wmma<1>(smbuf, g_gh, g_gl,
                     g_Wh + (size_t)3 * D * D, g_Wl + (size_t)3 * D * D,
                     bo, out, g_h, M);
}

// ============================================================
// zero wV / z accumulators
// ============================================================
__global__ void zero_kernel(int n_wv, int n_z)
{
    int i = blockIdx.x * blockDim.x + threadIdx.x;
    int stride = gridDim.x * blockDim.x;
    for (int j = i; j < n_wv; j += stride) g_wV[j] = 0.0f;
    for (int j = i; j < n_z;  j += stride) g_z[j]  = 0.0f;
}

// ============================================================
// edge kernel: one warp per edge.
// ============================================================
__global__ __launch_bounds__(256) void edge_kernel(
    const int* __restrict__ src, const int* __restrict__ dst, int E)
{
    int w = (int)((blockIdx.x * blockDim.x + threadIdx.x) >> 5);
    int lane = threadIdx.x & 31;
    if (w >= E) return;
    int s = src[w];
    int d = dst[w];

    const float4* Q4 = (const float4*)g_Q;
    const float4* K4 = (const float4*)g_K;
    const float4* V4 = (const float4*)g_V;

    float4 q = Q4[(size_t)d * 32 + lane];
    float4 k = K4[(size_t)s * 32 + lane];
    float4 v = V4[(size_t)s * 32 + lane];

    float p = q.x * k.x + q.y * k.y + q.z * k.z + q.w * k.w;
    p += __shfl_xor_sync(0xffffffffu, p, 1);
    p += __shfl_xor_sync(0xffffffffu, p, 2);
    float sc = p * 0.25f;                 // 1/sqrt(16)
    sc = fminf(fmaxf(sc, -5.0f), 5.0f);
    sc = expf(sc);

    if ((lane & 3) == 0) {
        float* zp = &g_z[(size_t)d * NHEADS + (lane >> 2)];
        asm volatile("red.global.add.f32 [%0], %1;" :: "l"(zp), "f"(sc) : "memory");
    }

    float* wp = &g_wV[(size_t)d * 128 + lane * 4];
    asm volatile("red.global.add.v4.f32 [%0], {%1,%2,%3,%4};"
                 :: "l"(wp), "f"(v.x * sc), "f"(v.y * sc), "f"(v.z * sc), "f"(v.w * sc)
                 : "memory");
}

// ============================================================
// attn normalize + residual + LN1 -> h ; LN2(h) -> g (+ bf16 split of g)
// ============================================================
__global__ __launch_bounds__(256) void attn_ln_kernel(
    const float* __restrict__ x,
    const float* __restrict__ gamma1, const float* __restrict__ beta1,
    const float* __restrict__ gamma2, const float* __restrict__ beta2, int M)
{
    int w = (int)((blockIdx.x * blockDim.x + threadIdx.x) >> 5);
    int lane = threadIdx.x & 31;
    if (w >= M) return;

    const float4* x4  = (const float4*)x;
    const float4* wv4 = (const float4*)g_wV;

    float4 xv = x4[(size_t)w * 32 + lane];
    float4 wv = wv4[(size_t)w * 32 + lane];
    float inv = 1.0f / (g_z[(size_t)w * NHEADS + (lane >> 2)] + 1e-3f);

    float4 y;
    y.x = xv.x + wv.x * inv;
    y.y = xv.y + wv.y * inv;
    y.z = xv.z + wv.z * inv;
    y.w = xv.w + wv.w * inv;

    float s  = y.x + y.y + y.z + y.w;
    float sq = y.x * y.x + y.y * y.y + y.z * y.z + y.w * y.w;
#pragma unroll
    for (int o = 16; o > 0; o >>= 1) {
        s  += __shfl_xor_sync(0xffffffffu, s, o);
        sq += __shfl_xor_sync(0xffffffffu, sq, o);
    }
    float mu   = s * (1.0f / 128.0f);
    float var  = sq * (1.0f / 128.0f) - mu * mu;
    float rstd = rsqrtf(var + 1e-5f);

    float4 g1 = ((const float4*)gamma1)[lane];
    float4 b1 = ((const float4*)beta1)[lane];
    float4 hv;
    hv.x = (y.x - mu) * rstd * g1.x + b1.x;
    hv.y = (y.y - mu) * rstd * g1.y + b1.y;
    hv.z = (y.z - mu) * rstd * g1.z + b1.z;
    hv.w = (y.w - mu) * rstd * g1.w + b1.w;
    ((float4*)g_h)[(size_t)w * 32 + lane] = hv;

    float s2  = hv.x + hv.y + hv.z + hv.w;
    float sq2 = hv.x * hv.x + hv.y * hv.y + hv.z * hv.z + hv.w * hv.w;
#pragma unroll
    for (int o = 16; o > 0; o >>= 1) {
        s2  += __shfl_xor_sync(0xffffffffu, s2, o);
        sq2 += __shfl_xor_sync(0xffffffffu, sq2, o);
    }
    float mu2   = s2 * (1.0f / 128.0f);
    float var2  = sq2 * (1.0f / 128.0f) - mu2 * mu2;
    float rstd2 = rsqrtf(var2 + 1e-5f);

    float4 g2 = ((const float4*)gamma2)[lane];
    float4 b2 = ((const float4*)beta2)[lane];
    float4 gv;
    gv.x = (hv.x - mu2) * rstd2 * g2.x + b2.x;
    gv.y = (hv.y - mu2) * rstd2 * g2.y + b2.y;
    gv.z = (hv.z - mu2) * rstd2 * g2.z + b2.z;
    gv.w = (hv.w - mu2) * rstd2 * g2.w + b2.w;
    ((float4*)g_g)[(size_t)w * 32 + lane] = gv;

    // bf16 hi/lo split of g for the wmma out-GEMM
    float vv[4] = {gv.x, gv.y, gv.z, gv.w};
    __nv_bfloat16 hh[4], ll[4];
#pragma unroll
    for (int u = 0; u < 4; u++) {
        hh[u] = __float2bfloat16(vv[u]);
        ll[u] = __float2bfloat16(vv[u] - __bfloat162float(hh[u]));
    }
    *(uint2*)&g_gh[(size_t)w * 128 + lane * 4] = *(uint2*)hh;
    *(uint2*)&g_gl[(size_t)w * 128 + lane * 4] = *(uint2*)ll;
}

// ============================================================
extern "C" void kernel_launch(void* const* d_in, const int* in_sizes, int n_in,
                              void* d_out, int out_size)
{
    const float* x      = (const float*)d_in[0];
    const int*   src    = (const int*)  d_in[1];
    const int*   dst    = (const int*)  d_in[2];
    const float* Wq     = (const float*)d_in[3];
    const float* bq     = (const float*)d_in[4];
    const float* Wk     = (const float*)d_in[5];
    const float* bk     = (const float*)d_in[6];
    const float* Wv     = (const float*)d_in[7];
    const float* bv     = (const float*)d_in[8];
    const float* Wo     = (const float*)d_in[9];
    const float* bo     = (const float*)d_in[10];
    const float* gamma1 = (const float*)d_in[11];
    const float* beta1  = (const float*)d_in[12];
    const float* gamma2 = (const float*)d_in[13];
    const float* beta2  = (const float*)d_in[14];
    float* out = (float*)d_out;

    int M = in_sizes[0] / 128;
    int E = in_sizes[1];
    int nblk = (M + 127) / 128;

    zero_kernel<<<512, 256>>>(M * 128, M * NHEADS);
    prep_w_kernel<<<4, 256>>>(Wq, Wk, Wv, Wo);
    split_x_kernel<<<512, 256>>>(x, M * 128);

    dim3 gq(nblk, 3);
    qkv_kernel<<<gq, 256>>>(x, Wq, bq, Wk, bk, Wv, bv, M);

    int edge_blocks = (E + 7) / 8;  // 8 warps/block
    edge_kernel<<<edge_blocks, 256>>>(src, dst, E);

    attn_ln_kernel<<<(M * 32 + 255) / 256, 256>>>(x, gamma1, beta1, gamma2, beta2, M);

    out_gemm_kernel<<<nblk, 256>>>(Wo, bo, out, M);
}

// round 9
// speedup vs baseline: 1.0969x; 1.0969x over previous
#include <cuda_runtime.h>
#include <cuda_bf16.h>
#include <mma.h>
#include <math.h>
#include <stdint.h>

using namespace nvcuda;

#define D 128
#define NHEADS 8
#define NMAX 50000

// blocks [0, FSPLIT) use FFMA body; [FSPLIT, nblk) use wmma bf16x3 body
#define FSPLIT 160

// ---- scratch (no allocations allowed; device globals) ----
__device__ float g_Q[NMAX * D];
__device__ float g_K[NMAX * D];
__device__ float g_V[NMAX * D];
__device__ float g_wV[NMAX * D];
__device__ float g_z[NMAX * NHEADS];
__device__ float g_h[NMAX * D];
__device__ float g_g[NMAX * D];
// precomputed bf16 hi/lo splits
__device__ __nv_bfloat16 g_xh[NMAX * D];
__device__ __nv_bfloat16 g_xl[NMAX * D];
__device__ __nv_bfloat16 g_gh[NMAX * D];
__device__ __nv_bfloat16 g_gl[NMAX * D];
__device__ __nv_bfloat16 g_Wh[4 * D * D];
__device__ __nv_bfloat16 g_Wl[4 * D * D];

// ============================================================
// shared-memory union layout (static, 37888 B -> 2 CTAs/SM)
//  FFMA:  As 32x129 f32 (16512 B) | Bs 32x128 f32 (16384 B) = 32896
//  WMMA:  Ah (10240) | Al (10240) | Bh (8704) | Bl (8704) = 37888
//         stage ALIASES Bh/Bl after mainloop (needs 10240 <= 17408)
// ============================================================
#define SM_BYTES 37888
#define W_AH 0
#define W_AL 10240
#define W_BH 20480
#define W_BL 29184
#define W_ST 20480   // stage aliases B tiles (dead after mainloop)
#define AS_LD 40     // bf16 elems (80 B row stride)
#define BS_LD 136    // bf16 elems (272 B row stride)
#define ST_LD 20     // f32 elems (80 B)

// ============================================================
// FFMA body (round-1 proven): 128x128 tile, 8x8 microtile
// ============================================================
template <int MODE>
__device__ __forceinline__ void gemm_ffma(
    char* smbuf,
    const float* __restrict__ A, const float* __restrict__ W,
    const float* __restrict__ bias, float* __restrict__ C,
    const float* __restrict__ R, int M)
{
    float (*As)[129] = reinterpret_cast<float(*)[129]>(smbuf);
    float (*Bs)[128] = reinterpret_cast<float(*)[128]>(smbuf + 16512);

    const int tid  = threadIdx.x;
    const int tx   = tid & 15;
    const int ty   = tid >> 4;
    const int row0 = blockIdx.x * 128;

    float acc[8][8];
#pragma unroll
    for (int i = 0; i < 8; i++)
#pragma unroll
        for (int j = 0; j < 8; j++) acc[i][j] = 0.0f;

    const int arow = tid >> 3;
    const int acol = (tid & 7) << 2;
    const int brow = tid >> 5;
    const int bcol = (tid & 31) << 2;

    for (int kk = 0; kk < 128; kk += 32) {
        __syncthreads();
#pragma unroll
        for (int p = 0; p < 4; p++) {
            int r = row0 + arow + p * 32;
            float4 v = make_float4(0.f, 0.f, 0.f, 0.f);
            if (r < M) v = *(const float4*)(A + (size_t)r * 128 + kk + acol);
            int m = arow + p * 32;
            As[acol + 0][m] = v.x;
            As[acol + 1][m] = v.y;
            As[acol + 2][m] = v.z;
            As[acol + 3][m] = v.w;
        }
#pragma unroll
        for (int p = 0; p < 4; p++) {
            int r = kk + brow + p * 8;
            *(float4*)&Bs[brow + p * 8][bcol] =
                *(const float4*)(W + (size_t)r * 128 + bcol);
        }
        __syncthreads();

#pragma unroll
        for (int k = 0; k < 32; k++) {
            float a[8];
#pragma unroll
            for (int i = 0; i < 8; i++) a[i] = As[k][ty * 8 + i];
            float4 b0 = *(float4*)&Bs[k][tx * 8];
            float4 b1 = *(float4*)&Bs[k][tx * 8 + 4];
            float b[8] = {b0.x, b0.y, b0.z, b0.w, b1.x, b1.y, b1.z, b1.w};
#pragma unroll
            for (int i = 0; i < 8; i++)
#pragma unroll
                for (int j = 0; j < 8; j++)
                    acc[i][j] = fmaf(a[i], b[j], acc[i][j]);
        }
    }

    const int c0 = tx * 8;
    float4 bb0 = *(const float4*)(bias + c0);
    float4 bb1 = *(const float4*)(bias + c0 + 4);
    float bb[8] = {bb0.x, bb0.y, bb0.z, bb0.w, bb1.x, bb1.y, bb1.z, bb1.w};
#pragma unroll
    for (int i = 0; i < 8; i++) {
        int r = row0 + ty * 8 + i;
        if (r >= M) continue;
        float v[8];
#pragma unroll
        for (int j = 0; j < 8; j++) {
            float val = acc[i][j] + bb[j];
            if (MODE == 1)
                val = R[(size_t)r * 128 + c0 + j] + fmaxf(val, 0.0f);
            v[j] = val;
        }
        *(float4*)(C + (size_t)r * 128 + c0)     = make_float4(v[0], v[1], v[2], v[3]);
        *(float4*)(C + (size_t)r * 128 + c0 + 4) = make_float4(v[4], v[5], v[6], v[7]);
    }
}

// ============================================================
// WMMA bf16x3 body with PRE-SPLIT bf16 inputs (no cvt in loop).
// 128x128 tile, 8 warps 2(m)x4(n), warp = 64x32, BK=32.
// ============================================================
template <int MODE>
__device__ __forceinline__ void gemm_wmma(
    char* smbuf,
    const __nv_bfloat16* __restrict__ Agh, const __nv_bfloat16* __restrict__ Agl,
    const __nv_bfloat16* __restrict__ Wgh, const __nv_bfloat16* __restrict__ Wgl,
    const float* __restrict__ bias, float* __restrict__ C,
    const float* __restrict__ R, int M)
{
    __nv_bfloat16* Ah = (__nv_bfloat16*)(smbuf + W_AH);
    __nv_bfloat16* Al = (__nv_bfloat16*)(smbuf + W_AL);
    __nv_bfloat16* Bh = (__nv_bfloat16*)(smbuf + W_BH);
    __nv_bfloat16* Bl = (__nv_bfloat16*)(smbuf + W_BL);

    const int tid    = threadIdx.x;
    const int warp   = tid >> 5;
    const int lane   = tid & 31;
    const int warp_m = warp & 1;
    const int warp_n = warp >> 1;
    const int row0   = blockIdx.x * 128;
    float* stg = (float*)(smbuf + W_ST) + warp * 16 * ST_LD;

    wmma::fragment<wmma::accumulator, 16, 16, 16, float> c[4][2];
#pragma unroll
    for (int im = 0; im < 4; im++)
#pragma unroll
        for (int jn = 0; jn < 2; jn++) wmma::fill_fragment(c[im][jn], 0.0f);

    const int arow = tid >> 1;          // 0..127
    const int acol = (tid & 1) * 16;    // 0 or 16
    const int brow = tid >> 3;          // 0..31
    const int bcol = (tid & 7) * 16;    // 0..112

    const uint4 zero4 = make_uint4(0u, 0u, 0u, 0u);

    for (int kk = 0; kk < 128; kk += 32) {
        __syncthreads();
        // A chunk [128 x 32] bf16 hi/lo: pure 16B copies
        {
            int r = row0 + arow;
            const uint4* sh = (const uint4*)(Agh + (size_t)r * 128 + kk + acol);
            const uint4* sl = (const uint4*)(Agl + (size_t)r * 128 + kk + acol);
            uint4* dh = (uint4*)(Ah + arow * AS_LD + acol);
            uint4* dl = (uint4*)(Al + arow * AS_LD + acol);
            if (r < M) {
                dh[0] = sh[0]; dh[1] = sh[1];
                dl[0] = sl[0]; dl[1] = sl[1];
            } else {
                dh[0] = zero4; dh[1] = zero4;
                dl[0] = zero4; dl[1] = zero4;
            }
        }
        // W chunk [32 x 128] bf16 hi/lo
        {
            const uint4* sh = (const uint4*)(Wgh + (size_t)(kk + brow) * 128 + bcol);
            const uint4* sl = (const uint4*)(Wgl + (size_t)(kk + brow) * 128 + bcol);
            uint4* dh = (uint4*)(Bh + brow * BS_LD + bcol);
            uint4* dl = (uint4*)(Bl + brow * BS_LD + bcol);
            dh[0] = sh[0]; dh[1] = sh[1];
            dl[0] = sl[0]; dl[1] = sl[1];
        }
        __syncthreads();

#pragma unroll
        for (int ks = 0; ks < 2; ks++) {
            const int k0 = ks * 16;
            wmma::fragment<wmma::matrix_b, 16, 16, 16, __nv_bfloat16, wmma::row_major> b_hi[2], b_lo[2];
#pragma unroll
            for (int jn = 0; jn < 2; jn++) {
                const int n0 = warp_n * 32 + jn * 16;
                wmma::load_matrix_sync(b_hi[jn], Bh + k0 * BS_LD + n0, BS_LD);
                wmma::load_matrix_sync(b_lo[jn], Bl + k0 * BS_LD + n0, BS_LD);
            }
#pragma unroll
            for (int im = 0; im < 4; im++) {
                const int m0 = warp_m * 64 + im * 16;
                wmma::fragment<wmma::matrix_a, 16, 16, 16, __nv_bfloat16, wmma::row_major> a_hi, a_lo;
                wmma::load_matrix_sync(a_hi, Ah + m0 * AS_LD + k0, AS_LD);
                wmma::load_matrix_sync(a_lo, Al + m0 * AS_LD + k0, AS_LD);
#pragma unroll
                for (int jn = 0; jn < 2; jn++) {
                    wmma::mma_sync(c[im][jn], a_hi, b_hi[jn], c[im][jn]);
                    wmma::mma_sync(c[im][jn], a_hi, b_lo[jn], c[im][jn]);
                    wmma::mma_sync(c[im][jn], a_lo, b_hi[jn], c[im][jn]);
                }
            }
        }
    }

    // B tiles are dead now; stage aliases them. Sync before reuse.
    __syncthreads();

    // epilogue via per-warp staging
    const int r  = lane >> 1;
    const int cc = (lane & 1) * 8;
#pragma unroll
    for (int im = 0; im < 4; im++) {
#pragma unroll
        for (int jn = 0; jn < 2; jn++) {
            wmma::store_matrix_sync(stg, c[im][jn], ST_LD, wmma::mem_row_major);
            __syncwarp();
            const int grow = row0 + warp_m * 64 + im * 16 + r;
            const int gcol = warp_n * 32 + jn * 16 + cc;
            if (grow < M) {
                float v[8];
#pragma unroll
                for (int u = 0; u < 8; u++) {
                    float val = stg[r * ST_LD + cc + u] + bias[gcol + u];
                    if (MODE == 1)
                        val = R[(size_t)grow * 128 + gcol + u] + fmaxf(val, 0.0f);
                    v[u] = val;
                }
                *(float4*)(C + (size_t)grow * 128 + gcol)     = make_float4(v[0], v[1], v[2], v[3]);
                *(float4*)(C + (size_t)grow * 128 + gcol + 4) = make_float4(v[4], v[5], v[6], v[7]);
            }
            __syncwarp();
        }
    }
}

// ============================================================
// fused prep: zero accumulators + split weights + split x
// blocks 0..507: zero + split_x (strided); blocks 508..511: weights
// ============================================================
__global__ __launch_bounds__(256) void prep_kernel(
    const float* __restrict__ x,
    const float* __restrict__ Wq, const float* __restrict__ Wk,
    const float* __restrict__ Wv, const float* __restrict__ Wo, int M)
{
    if (blockIdx.x >= 508) {
        int wi = blockIdx.x - 508;
        const float* W;
        switch (wi) {
            case 0: W = Wq; break;
            case 1: W = Wk; break;
            case 2: W = Wv; break;
            default: W = Wo; break;
        }
        __nv_bfloat16* oh = g_Wh + (size_t)wi * D * D;
        __nv_bfloat16* ol = g_Wl + (size_t)wi * D * D;
        for (int i = threadIdx.x; i < D * D; i += 256) {
            float v = W[i];
            __nv_bfloat16 h = __float2bfloat16(v);
            oh[i] = h;
            ol[i] = __float2bfloat16(v - __bfloat162float(h));
        }
        return;
    }
    int i = blockIdx.x * blockDim.x + threadIdx.x;
    int stride = 508 * blockDim.x;
    int n = M * D;
    for (int j = i; j < n; j += stride) {
        g_wV[j] = 0.0f;
        float v = x[j];
        __nv_bfloat16 h = __float2bfloat16(v);
        g_xh[j] = h;
        g_xl[j] = __float2bfloat16(v - __bfloat162float(h));
    }
    int nz = M * NHEADS;
    for (int j = i; j < nz; j += stride) g_z[j] = 0.0f;
}

// ============================================================
// hybrid GEMM kernels (2 CTAs/SM)
// ============================================================
__global__ __launch_bounds__(256, 2) void qkv_kernel(
    const float* __restrict__ x,
    const float* __restrict__ Wq, const float* __restrict__ bq,
    const float* __restrict__ Wk, const float* __restrict__ bk,
    const float* __restrict__ Wv, const float* __restrict__ bv, int M)
{
    __shared__ alignas(16) char smbuf[SM_BYTES];
    const float* W; const float* b; float* C; int wi;
    if (blockIdx.y == 0)      { W = Wq; b = bq; C = g_Q; wi = 0; }
    else if (blockIdx.y == 1) { W = Wk; b = bk; C = g_K; wi = 1; }
    else                      { W = Wv; b = bv; C = g_V; wi = 2; }
    if (blockIdx.x < FSPLIT)
        gemm_ffma<0>(smbuf, x, W, b, C, nullptr, M);
    else
        gemm_wmma<0>(smbuf, g_xh, g_xl,
                     g_Wh + (size_t)wi * D * D, g_Wl + (size_t)wi * D * D,
                     b, C, nullptr, M);
}

__global__ __launch_bounds__(256, 2) void out_gemm_kernel(
    const float* __restrict__ Wo, const float* __restrict__ bo,
    float* __restrict__ out, int M)
{
    __shared__ alignas(16) char smbuf[SM_BYTES];
    if (blockIdx.x < FSPLIT)
        gemm_ffma<1>(smbuf, g_g, Wo, bo, out, g_h, M);
    else
        gemm_wmma<1>(smbuf, g_gh, g_gl,
                     g_Wh + (size_t)3 * D * D, g_Wl + (size_t)3 * D * D,
                     bo, out, g_h, M);
}

// ============================================================
// edge kernel: one warp per edge.
// ============================================================
__global__ __launch_bounds__(256) void edge_kernel(
    const int* __restrict__ src, const int* __restrict__ dst, int E)
{
    int w = (int)((blockIdx.x * blockDim.x + threadIdx.x) >> 5);
    int lane = threadIdx.x & 31;
    if (w >= E) return;
    int s = src[w];
    int d = dst[w];

    const float4* Q4 = (const float4*)g_Q;
    const float4* K4 = (const float4*)g_K;
    const float4* V4 = (const float4*)g_V;

    float4 q = Q4[(size_t)d * 32 + lane];
    float4 k = K4[(size_t)s * 32 + lane];
    float4 v = V4[(size_t)s * 32 + lane];

    float p = q.x * k.x + q.y * k.y + q.z * k.z + q.w * k.w;
    p += __shfl_xor_sync(0xffffffffu, p, 1);
    p += __shfl_xor_sync(0xffffffffu, p, 2);
    float sc = p * 0.25f;                 // 1/sqrt(16)
    sc = fminf(fmaxf(sc, -5.0f), 5.0f);
    sc = expf(sc);

    if ((lane & 3) == 0) {
        float* zp = &g_z[(size_t)d * NHEADS + (lane >> 2)];
        asm volatile("red.global.add.f32 [%0], %1;" :: "l"(zp), "f"(sc) : "memory");
    }

    float* wp = &g_wV[(size_t)d * 128 + lane * 4];
    asm volatile("red.global.add.v4.f32 [%0], {%1,%2,%3,%4};"
                 :: "l"(wp), "f"(v.x * sc), "f"(v.y * sc), "f"(v.z * sc), "f"(v.w * sc)
                 : "memory");
}

// ============================================================
// attn normalize + residual + LN1 -> h ; LN2(h) -> g (+ bf16 split of g)
// ============================================================
__global__ __launch_bounds__(256) void attn_ln_kernel(
    const float* __restrict__ x,
    const float* __restrict__ gamma1, const float* __restrict__ beta1,
    const float* __restrict__ gamma2, const float* __restrict__ beta2, int M)
{
    int w = (int)((blockIdx.x * blockDim.x + threadIdx.x) >> 5);
    int lane = threadIdx.x & 31;
    if (w >= M) return;

    const float4* x4  = (const float4*)x;
    const float4* wv4 = (const float4*)g_wV;

    float4 xv = x4[(size_t)w * 32 + lane];
    float4 wv = wv4[(size_t)w * 32 + lane];
    float inv = 1.0f / (g_z[(size_t)w * NHEADS + (lane >> 2)] + 1e-3f);

    float4 y;
    y.x = xv.x + wv.x * inv;
    y.y = xv.y + wv.y * inv;
    y.z = xv.z + wv.z * inv;
    y.w = xv.w + wv.w * inv;

    float s  = y.x + y.y + y.z + y.w;
    float sq = y.x * y.x + y.y * y.y + y.z * y.z + y.w * y.w;
#pragma unroll
    for (int o = 16; o > 0; o >>= 1) {
        s  += __shfl_xor_sync(0xffffffffu, s, o);
        sq += __shfl_xor_sync(0xffffffffu, sq, o);
    }
    float mu   = s * (1.0f / 128.0f);
    float var  = sq * (1.0f / 128.0f) - mu * mu;
    float rstd = rsqrtf(var + 1e-5f);

    float4 g1 = ((const float4*)gamma1)[lane];
    float4 b1 = ((const float4*)beta1)[lane];
    float4 hv;
    hv.x = (y.x - mu) * rstd * g1.x + b1.x;
    hv.y = (y.y - mu) * rstd * g1.y + b1.y;
    hv.z = (y.z - mu) * rstd * g1.z + b1.z;
    hv.w = (y.w - mu) * rstd * g1.w + b1.w;
    ((float4*)g_h)[(size_t)w * 32 + lane] = hv;

    float s2  = hv.x + hv.y + hv.z + hv.w;
    float sq2 = hv.x * hv.x + hv.y * hv.y + hv.z * hv.z + hv.w * hv.w;
#pragma unroll
    for (int o = 16; o > 0; o >>= 1) {
        s2  += __shfl_xor_sync(0xffffffffu, s2, o);
        sq2 += __shfl_xor_sync(0xffffffffu, sq2, o);
    }
    float mu2   = s2 * (1.0f / 128.0f);
    float var2  = sq2 * (1.0f / 128.0f) - mu2 * mu2;
    float rstd2 = rsqrtf(var2 + 1e-5f);

    float4 g2 = ((const float4*)gamma2)[lane];
    float4 b2 = ((const float4*)beta2)[lane];
    float4 gv;
    gv.x = (hv.x - mu2) * rstd2 * g2.x + b2.x;
    gv.y = (hv.y - mu2) * rstd2 * g2.y + b2.y;
    gv.z = (hv.z - mu2) * rstd2 * g2.z + b2.z;
    gv.w = (hv.w - mu2) * rstd2 * g2.w + b2.w;
    ((float4*)g_g)[(size_t)w * 32 + lane] = gv;

    // bf16 hi/lo split of g for the wmma out-GEMM
    float vv[4] = {gv.x, gv.y, gv.z, gv.w};
    __nv_bfloat16 hh[4], ll[4];
#pragma unroll
    for (int u = 0; u < 4; u++) {
        hh[u] = __float2bfloat16(vv[u]);
        ll[u] = __float2bfloat16(vv[u] - __bfloat162float(hh[u]));
    }
    *(uint2*)&g_gh[(size_t)w * 128 + lane * 4] = *(uint2*)hh;
    *(uint2*)&g_gl[(size_t)w * 128 + lane * 4] = *(uint2*)ll;
}

// ============================================================
extern "C" void kernel_launch(void* const* d_in, const int* in_sizes, int n_in,
                              void* d_out, int out_size)
{
    const float* x      = (const float*)d_in[0];
    const int*   src    = (const int*)  d_in[1];
    const int*   dst    = (const int*)  d_in[2];
    const float* Wq     = (const float*)d_in[3];
    const float* bq     = (const float*)d_in[4];
    const float* Wk     = (const float*)d_in[5];
    const float* bk     = (const float*)d_in[6];
    const float* Wv     = (const float*)d_in[7];
    const float* bv     = (const float*)d_in[8];
    const float* Wo     = (const float*)d_in[9];
    const float* bo     = (const float*)d_in[10];
    const float* gamma1 = (const float*)d_in[11];
    const float* beta1  = (const float*)d_in[12];
    const float* gamma2 = (const float*)d_in[13];
    const float* beta2  = (const float*)d_in[14];
    float* out = (float*)d_out;

    int M = in_sizes[0] / 128;
    int E = in_sizes[1];
    int nblk = (M + 127) / 128;

    prep_kernel<<<512, 256>>>(x, Wq, Wk, Wv, Wo, M);

    dim3 gq(nblk, 3);
    qkv_kernel<<<gq, 256>>>(x, Wq, bq, Wk, bk, Wv, bv, M);

    int edge_blocks = (E + 7) / 8;  // 8 warps/block
    edge_kernel<<<edge_blocks, 256>>>(src, dst, E);

    attn_ln_kernel<<<(M * 32 + 255) / 256, 256>>>(x, gamma1, beta1, gamma2, beta2, M);

    out_gemm_kernel<<<nblk, 256>>>(Wo, bo, out, M);
}

// round 10
// speedup vs baseline: 1.3515x; 1.2322x over previous
#include <cuda_runtime.h>
#include <cuda_bf16.h>
#include <mma.h>
#include <math.h>
#include <stdint.h>

using namespace nvcuda;

#define D 128
#define NHEADS 8
#define NMAX 50000
#define EMAX 800000

// blocks [0, FSPLIT) use FFMA body; [FSPLIT, nblk) use wmma bf16x3 body
#define FSPLIT 160

// ---- scratch (no allocations allowed; device globals) ----
__device__ float g_Q[NMAX * D];
__device__ float g_K[NMAX * D];
__device__ float g_V[NMAX * D];
__device__ float g_h[NMAX * D];
__device__ float g_g[NMAX * D];
// precomputed bf16 hi/lo splits
__device__ __nv_bfloat16 g_xh[NMAX * D];
__device__ __nv_bfloat16 g_xl[NMAX * D];
__device__ __nv_bfloat16 g_gh[NMAX * D];
__device__ __nv_bfloat16 g_gl[NMAX * D];
__device__ __nv_bfloat16 g_Wh[4 * D * D];
__device__ __nv_bfloat16 g_Wl[4 * D * D];
// CSR by dst
__device__ int g_cnt[NMAX];
__device__ int g_off[NMAX];
__device__ int g_bsum[256];
__device__ int g_bsumx[256];
__device__ int g_esrc[EMAX];

// ============================================================
// shared-memory union layout (static, 37888 B -> 2 CTAs/SM)
// ============================================================
#define SM_BYTES 37888
#define W_AH 0
#define W_AL 10240
#define W_BH 20480
#define W_BL 29184
#define W_ST 20480   // stage aliases B tiles (dead after mainloop)
#define AS_LD 40
#define BS_LD 136
#define ST_LD 20

// ============================================================
// FFMA GEMM body
// ============================================================
template <int MODE>
__device__ __forceinline__ void gemm_ffma(
    char* smbuf,
    const float* __restrict__ A, const float* __restrict__ W,
    const float* __restrict__ bias, float* __restrict__ C,
    const float* __restrict__ R, int M)
{
    float (*As)[129] = reinterpret_cast<float(*)[129]>(smbuf);
    float (*Bs)[128] = reinterpret_cast<float(*)[128]>(smbuf + 16512);

    const int tid  = threadIdx.x;
    const int tx   = tid & 15;
    const int ty   = tid >> 4;
    const int row0 = blockIdx.x * 128;

    float acc[8][8];
#pragma unroll
    for (int i = 0; i < 8; i++)
#pragma unroll
        for (int j = 0; j < 8; j++) acc[i][j] = 0.0f;

    const int arow = tid >> 3;
    const int acol = (tid & 7) << 2;
    const int brow = tid >> 5;
    const int bcol = (tid & 31) << 2;

    for (int kk = 0; kk < 128; kk += 32) {
        __syncthreads();
#pragma unroll
        for (int p = 0; p < 4; p++) {
            int r = row0 + arow + p * 32;
            float4 v = make_float4(0.f, 0.f, 0.f, 0.f);
            if (r < M) v = *(const float4*)(A + (size_t)r * 128 + kk + acol);
            int m = arow + p * 32;
            As[acol + 0][m] = v.x;
            As[acol + 1][m] = v.y;
            As[acol + 2][m] = v.z;
            As[acol + 3][m] = v.w;
        }
#pragma unroll
        for (int p = 0; p < 4; p++) {
            int r = kk + brow + p * 8;
            *(float4*)&Bs[brow + p * 8][bcol] =
                *(const float4*)(W + (size_t)r * 128 + bcol);
        }
        __syncthreads();

#pragma unroll
        for (int k = 0; k < 32; k++) {
            float a[8];
#pragma unroll
            for (int i = 0; i < 8; i++) a[i] = As[k][ty * 8 + i];
            float4 b0 = *(float4*)&Bs[k][tx * 8];
            float4 b1 = *(float4*)&Bs[k][tx * 8 + 4];
            float b[8] = {b0.x, b0.y, b0.z, b0.w, b1.x, b1.y, b1.z, b1.w};
#pragma unroll
            for (int i = 0; i < 8; i++)
#pragma unroll
                for (int j = 0; j < 8; j++)
                    acc[i][j] = fmaf(a[i], b[j], acc[i][j]);
        }
    }

    const int c0 = tx * 8;
    float4 bb0 = *(const float4*)(bias + c0);
    float4 bb1 = *(const float4*)(bias + c0 + 4);
    float bb[8] = {bb0.x, bb0.y, bb0.z, bb0.w, bb1.x, bb1.y, bb1.z, bb1.w};
#pragma unroll
    for (int i = 0; i < 8; i++) {
        int r = row0 + ty * 8 + i;
        if (r >= M) continue;
        float v[8];
#pragma unroll
        for (int j = 0; j < 8; j++) {
            float val = acc[i][j] + bb[j];
            if (MODE == 1)
                val = R[(size_t)r * 128 + c0 + j] + fmaxf(val, 0.0f);
            v[j] = val;
        }
        *(float4*)(C + (size_t)r * 128 + c0)     = make_float4(v[0], v[1], v[2], v[3]);
        *(float4*)(C + (size_t)r * 128 + c0 + 4) = make_float4(v[4], v[5], v[6], v[7]);
    }
}

// ============================================================
// WMMA bf16x3 body (pre-split inputs)
// ============================================================
template <int MODE>
__device__ __forceinline__ void gemm_wmma(
    char* smbuf,
    const __nv_bfloat16* __restrict__ Agh, const __nv_bfloat16* __restrict__ Agl,
    const __nv_bfloat16* __restrict__ Wgh, const __nv_bfloat16* __restrict__ Wgl,
    const float* __restrict__ bias, float* __restrict__ C,
    const float* __restrict__ R, int M)
{
    __nv_bfloat16* Ah = (__nv_bfloat16*)(smbuf + W_AH);
    __nv_bfloat16* Al = (__nv_bfloat16*)(smbuf + W_AL);
    __nv_bfloat16* Bh = (__nv_bfloat16*)(smbuf + W_BH);
    __nv_bfloat16* Bl = (__nv_bfloat16*)(smbuf + W_BL);

    const int tid    = threadIdx.x;
    const int warp   = tid >> 5;
    const int lane   = tid & 31;
    const int warp_m = warp & 1;
    const int warp_n = warp >> 1;
    const int row0   = blockIdx.x * 128;
    float* stg = (float*)(smbuf + W_ST) + warp * 16 * ST_LD;

    wmma::fragment<wmma::accumulator, 16, 16, 16, float> c[4][2];
#pragma unroll
    for (int im = 0; im < 4; im++)
#pragma unroll
        for (int jn = 0; jn < 2; jn++) wmma::fill_fragment(c[im][jn], 0.0f);

    const int arow = tid >> 1;
    const int acol = (tid & 1) * 16;
    const int brow = tid >> 3;
    const int bcol = (tid & 7) * 16;

    const uint4 zero4 = make_uint4(0u, 0u, 0u, 0u);

    for (int kk = 0; kk < 128; kk += 32) {
        __syncthreads();
        {
            int r = row0 + arow;
            const uint4* sh = (const uint4*)(Agh + (size_t)r * 128 + kk + acol);
            const uint4* sl = (const uint4*)(Agl + (size_t)r * 128 + kk + acol);
            uint4* dh = (uint4*)(Ah + arow * AS_LD + acol);
            uint4* dl = (uint4*)(Al + arow * AS_LD + acol);
            if (r < M) {
                dh[0] = sh[0]; dh[1] = sh[1];
                dl[0] = sl[0]; dl[1] = sl[1];
            } else {
                dh[0] = zero4; dh[1] = zero4;
                dl[0] = zero4; dl[1] = zero4;
            }
        }
        {
            const uint4* sh = (const uint4*)(Wgh + (size_t)(kk + brow) * 128 + bcol);
            const uint4* sl = (const uint4*)(Wgl + (size_t)(kk + brow) * 128 + bcol);
            uint4* dh = (uint4*)(Bh + brow * BS_LD + bcol);
            uint4* dl = (uint4*)(Bl + brow * BS_LD + bcol);
            dh[0] = sh[0]; dh[1] = sh[1];
            dl[0] = sl[0]; dl[1] = sl[1];
        }
        __syncthreads();

#pragma unroll
        for (int ks = 0; ks < 2; ks++) {
            const int k0 = ks * 16;
            wmma::fragment<wmma::matrix_b, 16, 16, 16, __nv_bfloat16, wmma::row_major> b_hi[2], b_lo[2];
#pragma unroll
            for (int jn = 0; jn < 2; jn++) {
                const int n0 = warp_n * 32 + jn * 16;
                wmma::load_matrix_sync(b_hi[jn], Bh + k0 * BS_LD + n0, BS_LD);
                wmma::load_matrix_sync(b_lo[jn], Bl + k0 * BS_LD + n0, BS_LD);
            }
#pragma unroll
            for (int im = 0; im < 4; im++) {
                const int m0 = warp_m * 64 + im * 16;
                wmma::fragment<wmma::matrix_a, 16, 16, 16, __nv_bfloat16, wmma::row_major> a_hi, a_lo;
                wmma::load_matrix_sync(a_hi, Ah + m0 * AS_LD + k0, AS_LD);
                wmma::load_matrix_sync(a_lo, Al + m0 * AS_LD + k0, AS_LD);
#pragma unroll
                for (int jn = 0; jn < 2; jn++) {
                    wmma::mma_sync(c[im][jn], a_hi, b_hi[jn], c[im][jn]);
                    wmma::mma_sync(c[im][jn], a_hi, b_lo[jn], c[im][jn]);
                    wmma::mma_sync(c[im][jn], a_lo, b_hi[jn], c[im][jn]);
                }
            }
        }
    }

    __syncthreads();  // B tiles dead; stage aliases them

    const int r  = lane >> 1;
    const int cc = (lane & 1) * 8;
#pragma unroll
    for (int im = 0; im < 4; im++) {
#pragma unroll
        for (int jn = 0; jn < 2; jn++) {
            wmma::store_matrix_sync(stg, c[im][jn], ST_LD, wmma::mem_row_major);
            __syncwarp();
            const int grow = row0 + warp_m * 64 + im * 16 + r;
            const int gcol = warp_n * 32 + jn * 16 + cc;
            if (grow < M) {
                float v[8];
#pragma unroll
                for (int u = 0; u < 8; u++) {
                    float val = stg[r * ST_LD + cc + u] + bias[gcol + u];
                    if (MODE == 1)
                        val = R[(size_t)grow * 128 + gcol + u] + fmaxf(val, 0.0f);
                    v[u] = val;
                }
                *(float4*)(C + (size_t)grow * 128 + gcol)     = make_float4(v[0], v[1], v[2], v[3]);
                *(float4*)(C + (size_t)grow * 128 + gcol + 4) = make_float4(v[4], v[5], v[6], v[7]);
            }
            __syncwarp();
        }
    }
}

// ============================================================
// prep: zero cnt + split x + split weights
// ============================================================
__global__ __launch_bounds__(256) void prep_kernel(
    const float* __restrict__ x,
    const float* __restrict__ Wq, const float* __restrict__ Wk,
    const float* __restrict__ Wv, const float* __restrict__ Wo, int M)
{
    if (blockIdx.x >= 508) {
        int wi = blockIdx.x - 508;
        const float* W;
        switch (wi) {
            case 0: W = Wq; break;
            case 1: W = Wk; break;
            case 2: W = Wv; break;
            default: W = Wo; break;
        }
        __nv_bfloat16* oh = g_Wh + (size_t)wi * D * D;
        __nv_bfloat16* ol = g_Wl + (size_t)wi * D * D;
        for (int i = threadIdx.x; i < D * D; i += 256) {
            float v = W[i];
            __nv_bfloat16 h = __float2bfloat16(v);
            oh[i] = h;
            ol[i] = __float2bfloat16(v - __bfloat162float(h));
        }
        return;
    }
    int i = blockIdx.x * blockDim.x + threadIdx.x;
    int stride = 508 * blockDim.x;
    int n = M * D;
    for (int j = i; j < n; j += stride) {
        float v = x[j];
        __nv_bfloat16 h = __float2bfloat16(v);
        g_xh[j] = h;
        g_xl[j] = __float2bfloat16(v - __bfloat162float(h));
    }
    for (int j = i; j < M; j += stride) g_cnt[j] = 0;
}

// ============================================================
// CSR build: hist -> scan(3) -> scatter
// ============================================================
__global__ __launch_bounds__(256) void hist_kernel(const int* __restrict__ dst, int E)
{
    int i = blockIdx.x * blockDim.x + threadIdx.x;
    int stride = gridDim.x * blockDim.x;
    for (int e = i; e < E; e += stride)
        atomicAdd(&g_cnt[dst[e]], 1);
}

__device__ __forceinline__ int blk_scan_excl(int v, int* total)
{
    // 256-thread block exclusive scan (shfl-based)
    __shared__ int wsum[8];
    int lane = threadIdx.x & 31, w = threadIdx.x >> 5;
    int incl = v;
#pragma unroll
    for (int o = 1; o < 32; o <<= 1) {
        int t = __shfl_up_sync(0xffffffffu, incl, o);
        if (lane >= o) incl += t;
    }
    if (lane == 31) wsum[w] = incl;
    __syncthreads();
    if (threadIdx.x < 8) {
        int t = wsum[threadIdx.x];
        int s = t;
#pragma unroll
        for (int o = 1; o < 8; o <<= 1) {
            int u = __shfl_up_sync(0xffu, s, o);
            if (threadIdx.x >= o) s += u;
        }
        wsum[threadIdx.x] = s - t;  // exclusive warp offset
    }
    __syncthreads();
    int excl = incl - v + wsum[w];
    if (threadIdx.x == 255) *total = excl + v;
    return excl;
}

__global__ __launch_bounds__(256) void scan1_kernel(int M)
{
    __shared__ int tot;
    int i = blockIdx.x * 256 + threadIdx.x;
    int v = (i < M) ? g_cnt[i] : 0;
    int excl = blk_scan_excl(v, &tot);
    if (i < M) g_off[i] = excl;
    __syncthreads();
    if (threadIdx.x == 255) g_bsum[blockIdx.x] = tot;
}

__global__ __launch_bounds__(256) void scan2_kernel(int nb)
{
    __shared__ int tot;
    int t = threadIdx.x;
    int v = (t < nb) ? g_bsum[t] : 0;
    int excl = blk_scan_excl(v, &tot);
    if (t < nb) g_bsumx[t] = excl;
}

__global__ __launch_bounds__(256) void scan3_kernel(int M)
{
    int i = blockIdx.x * 256 + threadIdx.x;
    if (i < M) {
        g_off[i] += g_bsumx[blockIdx.x];
        g_cnt[i] = 0;
    }
}

__global__ __launch_bounds__(256) void scatter_kernel(
    const int* __restrict__ src, const int* __restrict__ dst, int E)
{
    int i = blockIdx.x * blockDim.x + threadIdx.x;
    int stride = gridDim.x * blockDim.x;
    for (int e = i; e < E; e += stride) {
        int d = dst[e];
        int p = g_off[d] + atomicAdd(&g_cnt[d], 1);
        g_esrc[p] = src[e];
    }
}

// ============================================================
// node kernel: warp per dst node.
// gather K/V over CSR edges, score vs Q[node], accumulate in regs,
// then attn-normalize + LN1 -> g_h, LN2 -> g_g (+ bf16 split).
// ============================================================
__global__ __launch_bounds__(256) void node_kernel(
    const float* __restrict__ x,
    const float* __restrict__ gamma1, const float* __restrict__ beta1,
    const float* __restrict__ gamma2, const float* __restrict__ beta2, int M)
{
    int node = (int)((blockIdx.x * blockDim.x + threadIdx.x) >> 5);
    int lane = threadIdx.x & 31;
    if (node >= M) return;

    const float4* Q4 = (const float4*)g_Q;
    const float4* K4 = (const float4*)g_K;
    const float4* V4 = (const float4*)g_V;

    float4 q = Q4[(size_t)node * 32 + lane];
    float4 wv = make_float4(0.f, 0.f, 0.f, 0.f);
    float z = 0.0f;

    const int beg = g_off[node];
    const int n   = g_cnt[node];
    const int* ep = g_esrc + beg;

    int j = 0;
    for (; j + 2 <= n; j += 2) {
        int s0 = ep[j], s1 = ep[j + 1];
        float4 k0 = K4[(size_t)s0 * 32 + lane];
        float4 v0 = V4[(size_t)s0 * 32 + lane];
        float4 k1 = K4[(size_t)s1 * 32 + lane];
        float4 v1 = V4[(size_t)s1 * 32 + lane];

        float p0 = q.x * k0.x + q.y * k0.y + q.z * k0.z + q.w * k0.w;
        float p1 = q.x * k1.x + q.y * k1.y + q.z * k1.z + q.w * k1.w;
        p0 += __shfl_xor_sync(0xffffffffu, p0, 1);
        p1 += __shfl_xor_sync(0xffffffffu, p1, 1);
        p0 += __shfl_xor_sync(0xffffffffu, p0, 2);
        p1 += __shfl_xor_sync(0xffffffffu, p1, 2);
        float sc0 = expf(fminf(fmaxf(p0 * 0.25f, -5.0f), 5.0f));
        float sc1 = expf(fminf(fmaxf(p1 * 0.25f, -5.0f), 5.0f));

        wv.x += v0.x * sc0 + v1.x * sc1;
        wv.y += v0.y * sc0 + v1.y * sc1;
        wv.z += v0.z * sc0 + v1.z * sc1;
        wv.w += v0.w * sc0 + v1.w * sc1;
        z += sc0 + sc1;
    }
    if (j < n) {
        int s0 = ep[j];
        float4 k0 = K4[(size_t)s0 * 32 + lane];
        float4 v0 = V4[(size_t)s0 * 32 + lane];
        float p0 = q.x * k0.x + q.y * k0.y + q.z * k0.z + q.w * k0.w;
        p0 += __shfl_xor_sync(0xffffffffu, p0, 1);
        p0 += __shfl_xor_sync(0xffffffffu, p0, 2);
        float sc0 = expf(fminf(fmaxf(p0 * 0.25f, -5.0f), 5.0f));
        wv.x += v0.x * sc0;
        wv.y += v0.y * sc0;
        wv.z += v0.z * sc0;
        wv.w += v0.w * sc0;
        z += sc0;
    }

    float inv = 1.0f / (z + 1e-3f);
    float4 xv = ((const float4*)x)[(size_t)node * 32 + lane];

    float4 y;
    y.x = xv.x + wv.x * inv;
    y.y = xv.y + wv.y * inv;
    y.z = xv.z + wv.z * inv;
    y.w = xv.w + wv.w * inv;

    float s  = y.x + y.y + y.z + y.w;
    float sq = y.x * y.x + y.y * y.y + y.z * y.z + y.w * y.w;
#pragma unroll
    for (int o = 16; o > 0; o >>= 1) {
        s  += __shfl_xor_sync(0xffffffffu, s, o);
        sq += __shfl_xor_sync(0xffffffffu, sq, o);
    }
    float mu   = s * (1.0f / 128.0f);
    float var  = sq * (1.0f / 128.0f) - mu * mu;
    float rstd = rsqrtf(var + 1e-5f);

    float4 g1 = ((const float4*)gamma1)[lane];
    float4 b1 = ((const float4*)beta1)[lane];
    float4 hv;
    hv.x = (y.x - mu) * rstd * g1.x + b1.x;
    hv.y = (y.y - mu) * rstd * g1.y + b1.y;
    hv.z = (y.z - mu) * rstd * g1.z + b1.z;
    hv.w = (y.w - mu) * rstd * g1.w + b1.w;
    ((float4*)g_h)[(size_t)node * 32 + lane] = hv;

    float s2  = hv.x + hv.y + hv.z + hv.w;
    float sq2 = hv.x * hv.x + hv.y * hv.y + hv.z * hv.z + hv.w * hv.w;
#pragma unroll
    for (int o = 16; o > 0; o >>= 1) {
        s2  += __shfl_xor_sync(0xffffffffu, s2, o);
        sq2 += __shfl_xor_sync(0xffffffffu, sq2, o);
    }
    float mu2   = s2 * (1.0f / 128.0f);
    float var2  = sq2 * (1.0f / 128.0f) - mu2 * mu2;
    float rstd2 = rsqrtf(var2 + 1e-5f);

    float4 g2 = ((const float4*)gamma2)[lane];
    float4 b2 = ((const float4*)beta2)[lane];
    float4 gv;
    gv.x = (hv.x - mu2) * rstd2 * g2.x + b2.x;
    gv.y = (hv.y - mu2) * rstd2 * g2.y + b2.y;
    gv.z = (hv.z - mu2) * rstd2 * g2.z + b2.z;
    gv.w = (hv.w - mu2) * rstd2 * g2.w + b2.w;
    ((float4*)g_g)[(size_t)node * 32 + lane] = gv;

    float vv[4] = {gv.x, gv.y, gv.z, gv.w};
    __nv_bfloat16 hh[4], ll[4];
#pragma unroll
    for (int u = 0; u < 4; u++) {
        hh[u] = __float2bfloat16(vv[u]);
        ll[u] = __float2bfloat16(vv[u] - __bfloat162float(hh[u]));
    }
    *(uint2*)&g_gh[(size_t)node * 128 + lane * 4] = *(uint2*)hh;
    *(uint2*)&g_gl[(size_t)node * 128 + lane * 4] = *(uint2*)ll;
}

// ============================================================
// hybrid GEMM kernels (2 CTAs/SM)
// ============================================================
__global__ __launch_bounds__(256, 2) void qkv_kernel(
    const float* __restrict__ x,
    const float* __restrict__ Wq, const float* __restrict__ bq,
    const float* __restrict__ Wk, const float* __restrict__ bk,
    const float* __restrict__ Wv, const float* __restrict__ bv, int M)
{
    __shared__ alignas(16) char smbuf[SM_BYTES];
    const float* W; const float* b; float* C; int wi;
    if (blockIdx.y == 0)      { W = Wq; b = bq; C = g_Q; wi = 0; }
    else if (blockIdx.y == 1) { W = Wk; b = bk; C = g_K; wi = 1; }
    else                      { W = Wv; b = bv; C = g_V; wi = 2; }
    if (blockIdx.x < FSPLIT)
        gemm_ffma<0>(smbuf, x, W, b, C, nullptr, M);
    else
        gemm_wmma<0>(smbuf, g_xh, g_xl,
                     g_Wh + (size_t)wi * D * D, g_Wl + (size_t)wi * D * D,
                     b, C, nullptr, M);
}

__global__ __launch_bounds__(256, 2) void out_gemm_kernel(
    const float* __restrict__ Wo, const float* __restrict__ bo,
    float* __restrict__ out, int M)
{
    __shared__ alignas(16) char smbuf[SM_BYTES];
    if (blockIdx.x < FSPLIT)
        gemm_ffma<1>(smbuf, g_g, Wo, bo, out, g_h, M);
    else
        gemm_wmma<1>(smbuf, g_gh, g_gl,
                     g_Wh + (size_t)3 * D * D, g_Wl + (size_t)3 * D * D,
                     bo, out, g_h, M);
}

// ============================================================
extern "C" void kernel_launch(void* const* d_in, const int* in_sizes, int n_in,
                              void* d_out, int out_size)
{
    const float* x      = (const float*)d_in[0];
    const int*   src    = (const int*)  d_in[1];
    const int*   dst    = (const int*)  d_in[2];
    const float* Wq     = (const float*)d_in[3];
    const float* bq     = (const float*)d_in[4];
    const float* Wk     = (const float*)d_in[5];
    const float* bk     = (const float*)d_in[6];
    const float* Wv     = (const float*)d_in[7];
    const float* bv     = (const float*)d_in[8];
    const float* Wo     = (const float*)d_in[9];
    const float* bo     = (const float*)d_in[10];
    const float* gamma1 = (const float*)d_in[11];
    const float* beta1  = (const float*)d_in[12];
    const float* gamma2 = (const float*)d_in[13];
    const float* beta2  = (const float*)d_in[14];
    float* out = (float*)d_out;

    int M = in_sizes[0] / 128;
    int E = in_sizes[1];
    int nblk = (M + 127) / 128;
    int nsb  = (M + 255) / 256;   // scan blocks (<= 256)

    prep_kernel<<<512, 256>>>(x, Wq, Wk, Wv, Wo, M);
    hist_kernel<<<512, 256>>>(dst, E);
    scan1_kernel<<<nsb, 256>>>(M);
    scan2_kernel<<<1, 256>>>(nsb);
    scan3_kernel<<<nsb, 256>>>(M);
    scatter_kernel<<<512, 256>>>(src, dst, E);

    dim3 gq(nblk, 3);
    qkv_kernel<<<gq, 256>>>(x, Wq, bq, Wk, bk, Wv, bv, M);

    node_kernel<<<(M * 32 + 255) / 256, 256>>>(x, gamma1, beta1, gamma2, beta2, M);

    out_gemm_kernel<<<nblk, 256>>>(Wo, bo, out, M);
}